// round 17
// baseline (speedup 1.0000x reference)
#include <cuda_runtime.h>
#include <cuda_fp16.h>
#include <cstdint>

#define IN_F   4096
#define OUT_F  4096
#define M_ROWS 512

#define BM 512                // all of M per CTA
#define BN 32                 // W strip per CTA -> each W element dequantized ONCE
#define BK 64                 // fp16 elems per ktile -> 128B rows
#define KT (IN_F / BK)        // 64
#define NTHR 512              // 16 warps: 8 along M x 2 along N, warp tile 64x16

// per-stage smem layout (bytes)
#define A_B   (BM * BK * 2)   // 65536
#define W_B   (BN * BK * 2)   // 4096
#define Q_B   (BN * BK * 4)   // 8192
#define O_B   (BN * BK * 4)   // 8192
#define G_B   (BN * BK * 4)   // 8192
#define A_OFF 0
#define W_OFF (A_B)
#define Q_OFF (W_OFF + W_B)
#define O_OFF (Q_OFF + Q_B)
#define G_OFF (O_OFF + O_B)
#define STAGE_B (A_B + W_B + Q_B + O_B + G_B)   // 94208 (1024-aligned)
#define SMEM_SIZE (2 * STAGE_B)                  // 184 KB

#define X_BLOCKS ((M_ROWS * IN_F / 4) / 256)     // 2048

// fp16 scratch: converted X [M_ROWS][IN_F]
__device__ __half g_X[(size_t)M_ROWS * IN_F];

// ---------------------------------------------------------------- helpers
__device__ __forceinline__ uint32_t s2u(const void* p) {
    uint32_t a;
    asm("{ .reg .u64 t; cvta.to.shared.u64 t, %1; cvt.u32.u64 %0, t; }" : "=r"(a) : "l"(p));
    return a;
}
__device__ __forceinline__ uint32_t swz(uint32_t b) { return b ^ ((b >> 3) & 0x70); }

__device__ __forceinline__ void cp_async16(uint32_t dst, const void* src) {
    asm volatile("cp.async.cg.shared.global [%0], [%1], 16;" :: "r"(dst), "l"(src));
}
__device__ __forceinline__ void cp_commit() { asm volatile("cp.async.commit_group;" ::: "memory"); }
template <int N> __device__ __forceinline__ void cp_wait() {
    asm volatile("cp.async.wait_group %0;" :: "n"(N) : "memory");
}

__device__ __forceinline__ void ldmatrix_x4(uint32_t* r, uint32_t addr) {
    asm volatile("ldmatrix.sync.aligned.m8n8.x4.shared.b16 {%0,%1,%2,%3}, [%4];"
                 : "=r"(r[0]), "=r"(r[1]), "=r"(r[2]), "=r"(r[3]) : "r"(addr));
}

__device__ __forceinline__ void mma_f16(float c[4], const uint32_t a[4],
                                        uint32_t b0, uint32_t b1) {
    asm volatile(
        "mma.sync.aligned.m16n8k16.row.col.f32.f16.f16.f32 "
        "{%0,%1,%2,%3}, {%4,%5,%6,%7}, {%8,%9}, {%0,%1,%2,%3};"
        : "+f"(c[0]), "+f"(c[1]), "+f"(c[2]), "+f"(c[3])
        : "r"(a[0]), "r"(a[1]), "r"(a[2]), "r"(a[3]), "r"(b0), "r"(b1));
}

// ---------------------------------------------------------------- pass 1: X fp32 -> fp16
__global__ void xcvt_kernel(const float* __restrict__ x) {
    size_t base = ((size_t)blockIdx.x * blockDim.x + threadIdx.x) * 4;
    float4 v = *reinterpret_cast<const float4*>(x + base);
    union { __half2 h[2]; uint2 u; } cv;
    cv.h[0] = __floats2half2_rn(v.x, v.y);
    cv.h[1] = __floats2half2_rn(v.z, v.w);
    *reinterpret_cast<uint2*>(g_X + base) = cv.u;
}

// ---------------------------------------------------------------- pass 2: fused dequant + GEMM
// Each CTA: N strip of 32 output cols, all M=512 rows. W dequantized once into smem.
__global__ __launch_bounds__(NTHR, 1)
void fused_kernel(const float* __restrict__ input,   // unused (g_X), kept for symmetry
                  const int* __restrict__ q,
                  const float* __restrict__ scales,
                  const float* __restrict__ zeros,
                  const float* __restrict__ outlier,
                  const float* __restrict__ grad,
                  const float* __restrict__ bias,
                  float* __restrict__ out) {
    extern __shared__ char smem_raw[];
    const uint32_t sbase = s2u(smem_raw);

    const int tid  = threadIdx.x;
    const int warp = tid >> 5;
    const int lane = tid & 31;
    const int bn   = blockIdx.x;  // 0..127

    const int m_base = (warp & 7) * 64;   // 8 warps along M
    const int n_base = (warp >> 3) * 16;  // 2 warps along N

    const int lm_r = lane & 15;
    const int lm_h = (lane >> 4) * 16;

    // dequant assignment: thread -> (n_t, 4 consecutive k)
    const int n_t = tid >> 4;          // 0..31
    const int kq  = (tid & 15) * 4;    // 0..60
    const int n_glob = bn * BN + n_t;
    const float s_n = __ldg(scales + n_glob);
    const float z_n = __ldg(zeros + n_glob);

    const __half* Abase = g_X;   // full X
    const size_t wrow = (size_t)n_glob * IN_F;

    float c[4][2][4];
    #pragma unroll
    for (int mi = 0; mi < 4; mi++)
        #pragma unroll
        for (int ni = 0; ni < 2; ni++)
            #pragma unroll
            for (int r = 0; r < 4; r++) c[mi][ni][r] = 0.0f;

    auto load_stage = [&](int kt, int s) {
        const uint32_t st = sbase + s * STAGE_B;
        // A: 512 rows x 8 chunks of 16B
        #pragma unroll
        for (int i = 0; i < 8; i++) {
            int idx = tid + i * NTHR;       // 0..4095
            int r = idx >> 3, ch = idx & 7;
            cp_async16(st + A_OFF + swz((uint32_t)(r * 128 + ch * 16)),
                       Abase + (size_t)r * IN_F + kt * BK + ch * 8);
        }
        // q/o/g: one 16B chunk per thread each (n = tid>>4, k4 = (tid&15)*4)
        {
            int n = tid >> 4, k4 = (tid & 15) * 4;
            size_t g = (size_t)(bn * BN + n) * IN_F + kt * BK + k4;
            uint32_t lo = (uint32_t)(n * 256 + k4 * 4);
            cp_async16(st + Q_OFF + lo, q + g);
            cp_async16(st + O_OFF + lo, outlier + g);
            cp_async16(st + G_OFF + lo, grad + g);
        }
        cp_commit();
    };

    load_stage(0, 0);

    for (int kt = 0; kt < KT; kt++) {
        const int s = kt & 1;
        cp_wait<0>();
        __syncthreads();  // stage s data visible; both buffers' consumers done

        if (kt + 1 < KT) load_stage(kt + 1, s ^ 1);

        const char* stp = smem_raw + s * STAGE_B;
        // inline dequant: q/o/g smem -> W fp16 smem (one vec4 per thread)
        {
            const int lo = n_t * 256 + kq * 4;
            int4   qv = *reinterpret_cast<const int4*>(stp + Q_OFF + lo);
            float4 ov = *reinterpret_cast<const float4*>(stp + O_OFF + lo);
            float4 gv = *reinterpret_cast<const float4*>(stp + G_OFF + lo);
            float w0 = ((float)qv.x - z_n) * s_n + ov.x * gv.x;
            float w1 = ((float)qv.y - z_n) * s_n + ov.y * gv.y;
            float w2 = ((float)qv.z - z_n) * s_n + ov.z * gv.z;
            float w3 = ((float)qv.w - z_n) * s_n + ov.w * gv.w;
            union { __half2 h[2]; uint2 u; } cv;
            cv.h[0] = __floats2half2_rn(w0, w1);
            cv.h[1] = __floats2half2_rn(w2, w3);
            *reinterpret_cast<uint2*>(const_cast<char*>(stp) + W_OFF +
                                      swz((uint32_t)(n_t * 128 + kq * 2))) = cv.u;
        }
        __syncthreads();  // W tile visible to all warps

        const uint32_t sA = sbase + s * STAGE_B + A_OFF;
        const uint32_t sW = sbase + s * STAGE_B + W_OFF;

        #pragma unroll
        for (int kk = 0; kk < 4; kk++) {  // 4 x k16
            const uint32_t kb = kk * 32 + lm_h;
            uint32_t a[4][4];
            #pragma unroll
            for (int mi = 0; mi < 4; mi++)
                ldmatrix_x4(a[mi], sA + swz((uint32_t)((m_base + mi * 16 + lm_r) * 128) + kb));
            uint32_t b[4];
            ldmatrix_x4(b, sW + swz((uint32_t)((n_base + lm_r) * 128) + kb));
            #pragma unroll
            for (int mi = 0; mi < 4; mi++)
                #pragma unroll
                for (int ni = 0; ni < 2; ni++)
                    mma_f16(c[mi][ni], a[mi], b[ni], b[ni + 2]);
        }
    }

    // epilogue
    const int gid = lane >> 2;
    const int tig = lane & 3;
    #pragma unroll
    for (int mi = 0; mi < 4; mi++) {
        int row0 = m_base + mi * 16 + gid;
        #pragma unroll
        for (int ni = 0; ni < 2; ni++) {
            int col = bn * BN + n_base + ni * 8 + tig * 2;
            float b0 = __ldg(bias + col), b1 = __ldg(bias + col + 1);
            float2 v;
            v.x = c[mi][ni][0] + b0;
            v.y = c[mi][ni][1] + b1;
            *reinterpret_cast<float2*>(out + (size_t)row0 * OUT_F + col) = v;
            v.x = c[mi][ni][2] + b0;
            v.y = c[mi][ni][3] + b1;
            *reinterpret_cast<float2*>(out + (size_t)(row0 + 8) * OUT_F + col) = v;
        }
    }
}

// ----------------------------------------------------------------
extern "C" void kernel_launch(void* const* d_in, const int* in_sizes, int n_in,
                              void* d_out, int out_size) {
    const float* input   = (const float*)d_in[0];
    const int*   qweight = (const int*)  d_in[1];
    const float* scales  = (const float*)d_in[2];
    const float* zeros   = (const float*)d_in[3];
    const float* outlier = (const float*)d_in[4];
    const float* grad    = (const float*)d_in[5];
    const float* bias    = (const float*)d_in[6];
    float*       out     = (float*)d_out;

    cudaFuncSetAttribute(fused_kernel, cudaFuncAttributeMaxDynamicSharedMemorySize, SMEM_SIZE);

    xcvt_kernel<<<X_BLOCKS, 256>>>(input);

    fused_kernel<<<OUT_F / BN, NTHR, SMEM_SIZE>>>(
        input, qweight, scales, zeros, outlier, grad, bias, out);
}